// round 10
// baseline (speedup 1.0000x reference)
#include <cuda_runtime.h>
#include <cuda_bf16.h>
#include <math.h>
#include <stdint.h>

#define N_TOK   8192
#define D_DIM   4096
#define N_EXP   64
#define CAP     160                          // ceil(1.25*8192/64)
#define NEC     (N_TOK * N_EXP * CAP)        // 83,886,080
#define FLAT    (N_TOK * 2)                  // 16384

#define TILE_K  64
#define GEMM_GRID (N_TOK / 64)               // 128 blocks, 64 tokens each

// dynamic smem layout (bytes)
#define XSD_OFF 0                            // x duplicated pairs [64][64] u64 = 32KB
#define GS_OFF  32768                        // gate tile [64][64] f32 = 16KB
#define SMEM_BYTES 49152
// logits overlay lg[64][68] f32 (17.4KB) sits on XSD after the mainloop.
#define LDS_S   68

typedef unsigned long long ull;

// ---------------- device scratch ------------------------------------------
__device__ __align__(16) float g_gate_t[D_DIM * N_EXP];      // gate^T [k][e]
__device__ __align__(16) unsigned char g_top_idx8[FLAT];
__device__ __align__(16) float g_top_w[FLAT];
__device__ __align__(16) float g_psum[N_EXP];

#define FMA2(d, a, b) asm("fma.rn.f32x2 %0, %1, %2, %0;" : "+l"(d) : "l"(a), "l"(b))
#define PACK2(d, s)   asm("mov.b64 %0, {%1, %1};" : "=l"(d) : "f"(s))
#define UNPACK2(lo, hi, s) asm("mov.b64 {%0, %1}, %2;" : "=f"(lo), "=f"(hi) : "l"(s))

// ---------------- zero-fill + scratch init --------------------------------
__global__ void __launch_bounds__(256)
k_zero(float4* __restrict__ zb, float* __restrict__ out_loss) {
    size_t i = (size_t)blockIdx.x * 256 + threadIdx.x;
    const float4 z = make_float4(0.f, 0.f, 0.f, 0.f);
#pragma unroll
    for (int j = 0; j < 80; j++) zb[i + (size_t)j * 524288] = z;
    if (blockIdx.x == 0) {
        if (threadIdx.x < N_EXP) g_psum[threadIdx.x] = 0.0f;
        if (threadIdx.x == 64) out_loss[0] = 0.0f;
    }
}

// ---------------- gate transpose ------------------------------------------
__global__ void k_transpose_gate(const float* __restrict__ gate_w) {
    int idx = blockIdx.x * blockDim.x + threadIdx.x;   // covers D*E
    int k = idx >> 6;
    int e = idx & 63;
    g_gate_t[idx] = gate_w[(size_t)e * D_DIM + k];
}

// ---------------- FFMA2 GEMM + softmax + top2 -----------------------------
// 128 blocks x 256 threads; block = 64 tokens x 64 experts; K-tile 64.
// x tile stored to SMEM pre-duplicated as (v,v) u64 pairs so the inner loop
// needs no PACK movs: 2 LDS.64 + 2 LDS.128 + 8 FFMA2 per kk.
__global__ void __launch_bounds__(256)
k_gemm(const float* __restrict__ x, float* __restrict__ probs_out) {
    extern __shared__ __align__(16) char dsm[];
    ull   (*xsd)[64] = (ull(*)[64])(dsm + XSD_OFF);
    float (*gs)[64]  = (float(*)[64])(dsm + GS_OFF);
    float (*lg)[LDS_S] = (float(*)[LDS_S])(dsm + XSD_OFF);  // post-loop overlay
    __shared__ float smax[64], sinv[64];

    const int tid = threadIdx.x;
    const int tx = tid & 7;            // expert octet (8 experts)
    const int ty = tid >> 3;           // token pair (2 tokens)
    const int n0 = blockIdx.x * 64;

    ull acc0[4], acc1[4];
#pragma unroll
    for (int j = 0; j < 4; j++) { acc0[j] = 0ull; acc1[j] = 0ull; }

    // register prefetch of tile 0
    float4 px[4], pg[4];
#pragma unroll
    for (int l = 0; l < 4; l++) {
        int idx = tid + l * 256;
        int r = idx >> 4, q = (idx & 15) * 4;
        px[l] = *(const float4*)&x[(size_t)(n0 + r) * D_DIM + q];
        pg[l] = *(const float4*)&g_gate_t[(size_t)r * N_EXP + q];
    }

    for (int kc = 0; kc < D_DIM; kc += TILE_K) {
        // ---- store prefetched tiles: x duplicated pairs, gate raw --------
#pragma unroll
        for (int l = 0; l < 4; l++) {
            int idx = tid + l * 256;
            int r = idx >> 4, q = (idx & 15) * 4;
            ull d0, d1, d2, d3;
            PACK2(d0, px[l].x); PACK2(d1, px[l].y);
            PACK2(d2, px[l].z); PACK2(d3, px[l].w);
            ull* dst = &xsd[r][q];
            *(ulonglong2*)&dst[0] = make_ulonglong2(d0, d1);
            *(ulonglong2*)&dst[2] = make_ulonglong2(d2, d3);
            *(float4*)&gs[r][q] = pg[l];
        }
        __syncthreads();

        // ---- prefetch next tile (overlaps FFMA mainloop) -----------------
        if (kc + TILE_K < D_DIM) {
#pragma unroll
            for (int l = 0; l < 4; l++) {
                int idx = tid + l * 256;
                int r = idx >> 4, q = (idx & 15) * 4;
                px[l] = *(const float4*)
                    &x[(size_t)(n0 + r) * D_DIM + kc + TILE_K + q];
                pg[l] = *(const float4*)
                    &g_gate_t[(size_t)(kc + TILE_K + r) * N_EXP + q];
            }
        }

        // ---- mainloop: 12 instr per kk for 32 MACs -----------------------
#pragma unroll 8
        for (int kk = 0; kk < TILE_K; kk++) {
            ull pa0 = xsd[2 * ty][kk];
            ull pa1 = xsd[2 * ty + 1][kk];
            ulonglong2 gA = *(const ulonglong2*)&gs[kk][tx * 8];
            ulonglong2 gB = *(const ulonglong2*)&gs[kk][tx * 8 + 4];
            FMA2(acc0[0], pa0, gA.x); FMA2(acc0[1], pa0, gA.y);
            FMA2(acc0[2], pa0, gB.x); FMA2(acc0[3], pa0, gB.y);
            FMA2(acc1[0], pa1, gA.x); FMA2(acc1[1], pa1, gA.y);
            FMA2(acc1[2], pa1, gB.x); FMA2(acc1[3], pa1, gB.y);
        }
        __syncthreads();
    }

    // ---- stage logits into shared (stride-68 overlay on xsd) -------------
#pragma unroll
    for (int j = 0; j < 4; j++) {
        float lo, hi;
        UNPACK2(lo, hi, acc0[j]);
        lg[2 * ty][tx * 8 + 2 * j]     = lo;
        lg[2 * ty][tx * 8 + 2 * j + 1] = hi;
        UNPACK2(lo, hi, acc1[j]);
        lg[2 * ty + 1][tx * 8 + 2 * j]     = lo;
        lg[2 * ty + 1][tx * 8 + 2 * j + 1] = hi;
    }
    __syncthreads();

    // ---- per-token softmax stats + exact top-2 ---------------------------
    if (tid < 64) {
        const int t = tid;
        float m = -INFINITY;
#pragma unroll
        for (int e = 0; e < N_EXP; e++) m = fmaxf(m, lg[t][e]);
        float s = 0.0f;
#pragma unroll
        for (int e = 0; e < N_EXP; e++) s += expf(lg[t][e] - m);
        float inv = 1.0f / s;
        smax[t] = m;
        sinv[t] = inv;

        float v1 = -INFINITY, v2 = -INFINITY;
        int i1 = 0, i2 = 0;
#pragma unroll
        for (int e = 0; e < N_EXP; e++) {
            float v = lg[t][e];
            if (v > v1) { v2 = v1; i2 = i1; v1 = v; i1 = e; }
            else if (v > v2) { v2 = v; i2 = e; }
        }
        float p1 = expf(v1 - m) * inv;
        float p2 = expf(v2 - m) * inv;
        float r = 1.0f / (p1 + p2);
        int n = n0 + t;
        g_top_idx8[2 * n]     = (unsigned char)i1;
        g_top_idx8[2 * n + 1] = (unsigned char)i2;
        g_top_w[2 * n]     = p1 * r;
        g_top_w[2 * n + 1] = p2 * r;
    }
    __syncthreads();

    // ---- probs: 1 token x 16 experts per thread; keep p in lg ------------
    {
        int t = tid >> 2;
        int e0 = (tid & 3) * 16;
        float m = smax[t], inv = sinv[t];
        float buf[16];
#pragma unroll
        for (int i = 0; i < 16; i++) buf[i] = expf(lg[t][e0 + i] - m) * inv;
        float4* dst = (float4*)&probs_out[(size_t)(n0 + t) * N_EXP + e0];
#pragma unroll
        for (int q = 0; q < 4; q++)
            dst[q] = make_float4(buf[4 * q], buf[4 * q + 1],
                                 buf[4 * q + 2], buf[4 * q + 3]);
#pragma unroll
        for (int i = 0; i < 16; i++) lg[t][e0 + i] = buf[i];
    }
    __syncthreads();

    if (tid < 64) {
        const int e = tid;
        float s = 0.0f;
#pragma unroll
        for (int t = 0; t < 64; t++) s += lg[t][e];
        atomicAdd(&g_psum[e], s);
    }
}

// ---------------- scan + scatter + loss (one block per expert) ------------
__global__ void __launch_bounds__(256)
k_scan_scatter_loss(float* __restrict__ out_mask,
                    float* __restrict__ out_comb,
                    float* __restrict__ out_loss) {
    __shared__ int warp_sums[8];
    const int e = blockIdx.x;
    const int tid = threadIdx.x;
    const int lane = tid & 31;
    const int wid = tid >> 5;

    uint4 wv[4];
#pragma unroll
    for (int i = 0; i < 4; i++)
        wv[i] = ((const uint4*)g_top_idx8)[tid * 4 + i];
    unsigned w[16];
#pragma unroll
    for (int i = 0; i < 4; i++) {
        w[4 * i + 0] = wv[i].x; w[4 * i + 1] = wv[i].y;
        w[4 * i + 2] = wv[i].z; w[4 * i + 3] = wv[i].w;
    }

    const unsigned eb = (unsigned)e * 0x01010101u;
    int local = 0;
#pragma unroll
    for (int i = 0; i < 16; i++) local += __popc(__vcmpeq4(w[i], eb));
    local >>= 3;

    int incl = local;
#pragma unroll
    for (int off = 1; off < 32; off <<= 1) {
        int v = __shfl_up_sync(0xffffffffu, incl, off);
        if (lane >= off) incl += v;
    }
    if (lane == 31) warp_sums[wid] = incl;
    __syncthreads();
    int base = 0;
#pragma unroll
    for (int j = 0; j < 8; j++) base += (j < wid) ? warp_sums[j] : 0;

    int c = base + incl - local;   // exclusive prefix for this thread
#pragma unroll
    for (int i = 0; i < 16; i++) {
        unsigned word = w[i];
#pragma unroll
        for (int b = 0; b < 4; b++) {
            if (((word >> (8 * b)) & 0xffu) == (unsigned)e) {
                if (c < CAP) {
                    int fi = tid * 64 + i * 4 + b;
                    size_t off = (size_t)(fi >> 1) * (N_EXP * CAP)
                               + (size_t)e * CAP + c;
                    out_mask[off] = 1.0f;
                    out_comb[off] = g_top_w[fi];
                }
                c++;
            }
        }
    }
    if (tid == 255) {
        int total = base + incl;
        float f = (float)total / (float)FLAT;
        float p = g_psum[e] / (float)N_TOK;
        atomicAdd(out_loss, 0.01f * (float)N_EXP * f * p);
    }
}

// ---------------- launch ---------------------------------------------------
extern "C" void kernel_launch(void* const* d_in, const int* in_sizes, int n_in,
                              void* d_out, int out_size) {
    const float* x      = (const float*)d_in[0];
    const float* gate_w = (const float*)d_in[1];
    float* out = (float*)d_out;

    float* out_mask  = out;                                   // N*E*C
    float* out_comb  = out + (size_t)NEC;                     // N*E*C
    float* out_probs = out + (size_t)2 * NEC;                 // N*E
    float* out_loss  = out + (size_t)2 * NEC + (size_t)N_TOK * N_EXP;

    cudaFuncSetAttribute(k_gemm,
        cudaFuncAttributeMaxDynamicSharedMemorySize, SMEM_BYTES);

    k_zero<<<2048, 256>>>((float4*)out, out_loss);
    k_transpose_gate<<<(D_DIM * N_EXP) / 256, 256>>>(gate_w);
    k_gemm<<<GEMM_GRID, 256, SMEM_BYTES>>>(x, out_probs);
    k_scan_scatter_loss<<<N_EXP, 256>>>(out_mask, out_comb, out_loss);
}

// round 11
// speedup vs baseline: 1.7862x; 1.7862x over previous
#include <cuda_runtime.h>
#include <cuda_bf16.h>
#include <math.h>
#include <stdint.h>

#define N_TOK   8192
#define D_DIM   4096
#define N_EXP   64
#define CAP     160                          // ceil(1.25*8192/64)
#define NEC     (N_TOK * N_EXP * CAP)        // 83,886,080
#define FLAT    (N_TOK * 2)                  // 16384

#define TILE_K  64
#define ZERO_BLOCKS 20
#define GRID_TOTAL  148                      // 20 zero + 128 GEMM = 1 CTA/SM
#define LDS_S   68                           // smem row stride (floats)

// zero-fill tickets: 64KB each (4096 float4), per-warp
#define ZCHUNK4  4096
#define NCHUNKS  (2u * NEC / 4u / ZCHUNK4)   // 10240

// dynamic smem layout (u32 units) — same as R9
#define XB_OFF  0                            // x big   [64][68]
#define XS_OFF  4352                         // x small
#define GB_OFF  8704                         // gate big
#define GS_OFF  13056                        // gate small
#define SMEM_U32 17408
#define SMEM_BYTES (SMEM_U32 * 4)            // 69,632

// ---------------- device scratch ------------------------------------------
__device__ __align__(16) float g_gate_t[D_DIM * N_EXP];      // gate^T [k][e]
__device__ __align__(16) unsigned char g_top_idx8[FLAT];
__device__ __align__(16) float g_top_w[FLAT];
__device__ __align__(16) float g_psum[N_EXP];
__device__ __align__(16) unsigned g_zctr;

__device__ __forceinline__ unsigned f2tf(float f) {
    unsigned r;
    asm("cvt.rna.tf32.f32 %0, %1;" : "=r"(r) : "f"(f));
    return r;
}
#define MMA_TF32(c0, c1, c2, c3, a0, a1, a2, a3, b0, b1)                      \
    asm volatile(                                                             \
        "mma.sync.aligned.m16n8k8.row.col.f32.tf32.tf32.f32 "                 \
        "{%0,%1,%2,%3}, {%4,%5,%6,%7}, {%8,%9}, {%0,%1,%2,%3};"               \
        : "+f"(c0), "+f"(c1), "+f"(c2), "+f"(c3)                              \
        : "r"(a0), "r"(a1), "r"(a2), "r"(a3), "r"(b0), "r"(b1))

// ---------------- gate transpose + all scratch init -----------------------
__global__ void k_transpose_gate(const float* __restrict__ gate_w,
                                 float* __restrict__ out_loss) {
    int idx = blockIdx.x * blockDim.x + threadIdx.x;   // covers D*E
    int k = idx >> 6;
    int e = idx & 63;
    g_gate_t[idx] = gate_w[(size_t)e * D_DIM + k];
    if (blockIdx.x == 0) {
        if (threadIdx.x < N_EXP) g_psum[threadIdx.x] = 0.0f;
        if (threadIdx.x == 64) g_zctr = 0u;
        if (threadIdx.x == 65) out_loss[0] = 0.0f;
    }
}

// ---------------- per-warp zero-fill steal loop ---------------------------
__device__ __forceinline__ void zero_steal(float4* __restrict__ zb) {
    const int lane = threadIdx.x & 31;
    const float4 z = make_float4(0.f, 0.f, 0.f, 0.f);
    for (;;) {
        unsigned c;
        if (lane == 0) c = atomicAdd(&g_zctr, 1u);
        c = __shfl_sync(0xffffffffu, c, 0);
        if (c >= NCHUNKS) return;
        float4* p = zb + (size_t)c * ZCHUNK4 + lane;
#pragma unroll 8
        for (int j = 0; j < ZCHUNK4 / 32; j++) p[j * 32] = z;
    }
}

// ---------------- mega: 20 zero-worker blocks + 128 HMMA GEMM blocks ------
__global__ void __launch_bounds__(256)
k_mega(const float* __restrict__ x, float* __restrict__ probs_out,
       float* __restrict__ out_zero_base /* mask+comb = 2*NEC floats */) {
    extern __shared__ unsigned sm[];
    __shared__ float smax[64], sinv[64];

    const int tid  = threadIdx.x;

    if (blockIdx.x < ZERO_BLOCKS) {      // -------- dedicated zero SMs -----
        zero_steal((float4*)out_zero_base);
        return;
    }

    // ----------------------------- GEMM (R9) -----------------------------
    const int wid  = tid >> 5;
    const int lane = tid & 31;
    const int n0   = (blockIdx.x - ZERO_BLOCKS) * 64;

    const int wm = (wid & 3) * 16;       // token offset within block tile
    const int wn = (wid >> 2) * 32;      // expert offset

    float c[4][4];
#pragma unroll
    for (int nt = 0; nt < 4; nt++)
#pragma unroll
        for (int j = 0; j < 4; j++) c[nt][j] = 0.0f;

    const int g  = lane >> 2;            // 0..7
    const int t4 = lane & 3;             // 0..3
    const unsigned abase = (unsigned)((wm + g) * LDS_S + t4);
    const unsigned bbase = (unsigned)(t4 * LDS_S + wn + g);

    for (int kc = 0; kc < D_DIM; kc += TILE_K) {
#pragma unroll
        for (int l = 0; l < 4; l++) {
            int idx = tid + l * 256;
            int r = idx >> 4, q = (idx & 15) * 4;
            float4 v = *(const float4*)&x[(size_t)(n0 + r) * D_DIM + kc + q];
            unsigned b0 = f2tf(v.x), b1 = f2tf(v.y),
                     b2 = f2tf(v.z), b3 = f2tf(v.w);
            unsigned s0 = f2tf(v.x - __uint_as_float(b0));
            unsigned s1 = f2tf(v.y - __uint_as_float(b1));
            unsigned s2 = f2tf(v.z - __uint_as_float(b2));
            unsigned s3 = f2tf(v.w - __uint_as_float(b3));
            *(uint4*)&sm[XB_OFF + r * LDS_S + q] = make_uint4(b0, b1, b2, b3);
            *(uint4*)&sm[XS_OFF + r * LDS_S + q] = make_uint4(s0, s1, s2, s3);

            float4 w = *(const float4*)&g_gate_t[(size_t)(kc + r) * N_EXP + q];
            unsigned gb0 = f2tf(w.x), gb1 = f2tf(w.y),
                     gb2 = f2tf(w.z), gb3 = f2tf(w.w);
            unsigned gs0 = f2tf(w.x - __uint_as_float(gb0));
            unsigned gs1 = f2tf(w.y - __uint_as_float(gb1));
            unsigned gs2 = f2tf(w.z - __uint_as_float(gb2));
            unsigned gs3 = f2tf(w.w - __uint_as_float(gb3));
            *(uint4*)&sm[GB_OFF + r * LDS_S + q] = make_uint4(gb0, gb1, gb2, gb3);
            *(uint4*)&sm[GS_OFF + r * LDS_S + q] = make_uint4(gs0, gs1, gs2, gs3);
        }
        __syncthreads();

#pragma unroll
        for (int ks = 0; ks < 8; ks++) {
            const unsigned ao = abase + ks * 8;
            const unsigned bo = bbase + ks * 8 * LDS_S;
            unsigned ab0 = sm[XB_OFF + ao];
            unsigned ab1 = sm[XB_OFF + ao + 8 * LDS_S];
            unsigned ab2 = sm[XB_OFF + ao + 4];
            unsigned ab3 = sm[XB_OFF + ao + 8 * LDS_S + 4];
            unsigned as0 = sm[XS_OFF + ao];
            unsigned as1 = sm[XS_OFF + ao + 8 * LDS_S];
            unsigned as2 = sm[XS_OFF + ao + 4];
            unsigned as3 = sm[XS_OFF + ao + 8 * LDS_S + 4];
#pragma unroll
            for (int nt = 0; nt < 4; nt++) {
                unsigned bn = bo + nt * 8;
                unsigned bb0 = sm[GB_OFF + bn];
                unsigned bb1 = sm[GB_OFF + bn + 4 * LDS_S];
                unsigned bs0 = sm[GS_OFF + bn];
                unsigned bs1 = sm[GS_OFF + bn + 4 * LDS_S];
                MMA_TF32(c[nt][0], c[nt][1], c[nt][2], c[nt][3],
                         ab0, ab1, ab2, ab3, bb0, bb1);
                MMA_TF32(c[nt][0], c[nt][1], c[nt][2], c[nt][3],
                         ab0, ab1, ab2, ab3, bs0, bs1);
                MMA_TF32(c[nt][0], c[nt][1], c[nt][2], c[nt][3],
                         as0, as1, as2, as3, bb0, bb1);
            }
        }
        __syncthreads();
    }

    // ---- stage logits into smem (reuse XB region), [64][68] --------------
    float* lg = (float*)sm;
    {
        const int r0 = wm + g;
#pragma unroll
        for (int nt = 0; nt < 4; nt++) {
            int col = wn + nt * 8 + 2 * t4;
            lg[r0 * LDS_S + col]           = c[nt][0];
            lg[r0 * LDS_S + col + 1]       = c[nt][1];
            lg[(r0 + 8) * LDS_S + col]     = c[nt][2];
            lg[(r0 + 8) * LDS_S + col + 1] = c[nt][3];
        }
    }
    __syncthreads();

    // ---- per-token softmax stats + exact top-2 ---------------------------
    if (tid < 64) {
        const int t = tid;
        float m = -INFINITY;
#pragma unroll
        for (int e = 0; e < N_EXP; e++) m = fmaxf(m, lg[t * LDS_S + e]);
        float s = 0.0f;
#pragma unroll
        for (int e = 0; e < N_EXP; e++) s += expf(lg[t * LDS_S + e] - m);
        float inv = 1.0f / s;
        smax[t] = m;
        sinv[t] = inv;

        float v1 = -INFINITY, v2 = -INFINITY;
        int i1 = 0, i2 = 0;
#pragma unroll
        for (int e = 0; e < N_EXP; e++) {
            float v = lg[t * LDS_S + e];
            if (v > v1) { v2 = v1; i2 = i1; v1 = v; i1 = e; }
            else if (v > v2) { v2 = v; i2 = e; }
        }
        float p1 = expf(v1 - m) * inv;
        float p2 = expf(v2 - m) * inv;
        float r = 1.0f / (p1 + p2);
        int n = n0 + t;
        g_top_idx8[2 * n]     = (unsigned char)i1;
        g_top_idx8[2 * n + 1] = (unsigned char)i2;
        g_top_w[2 * n]     = p1 * r;
        g_top_w[2 * n + 1] = p2 * r;
    }
    __syncthreads();

    // ---- probs: 1 token x 16 experts per thread; keep p in lg ------------
    {
        int t = tid >> 2;
        int e0 = (tid & 3) * 16;
        float m = smax[t], inv = sinv[t];
        float buf[16];
#pragma unroll
        for (int i = 0; i < 16; i++)
            buf[i] = expf(lg[t * LDS_S + e0 + i] - m) * inv;
        float4* dst = (float4*)&probs_out[(size_t)(n0 + t) * N_EXP + e0];
#pragma unroll
        for (int q = 0; q < 4; q++)
            dst[q] = make_float4(buf[4 * q], buf[4 * q + 1],
                                 buf[4 * q + 2], buf[4 * q + 3]);
#pragma unroll
        for (int i = 0; i < 16; i++) lg[t * LDS_S + e0 + i] = buf[i];
    }
    __syncthreads();

    if (tid < 64) {
        const int e = tid;
        float s = 0.0f;
#pragma unroll
        for (int t = 0; t < 64; t++) s += lg[t * LDS_S + e];
        atomicAdd(&g_psum[e], s);
    }
    __syncthreads();

    // ---- join the zero-fill steal loop (self-balancing tail) -------------
    zero_steal((float4*)out_zero_base);
}

// ---------------- scan + scatter + loss (one block per expert) ------------
__global__ void __launch_bounds__(256)
k_scan_scatter_loss(float* __restrict__ out_mask,
                    float* __restrict__ out_comb,
                    float* __restrict__ out_loss) {
    __shared__ int warp_sums[8];
    const int e = blockIdx.x;
    const int tid = threadIdx.x;
    const int lane = tid & 31;
    const int wid = tid >> 5;

    uint4 wv[4];
#pragma unroll
    for (int i = 0; i < 4; i++)
        wv[i] = ((const uint4*)g_top_idx8)[tid * 4 + i];
    unsigned w[16];
#pragma unroll
    for (int i = 0; i < 4; i++) {
        w[4 * i + 0] = wv[i].x; w[4 * i + 1] = wv[i].y;
        w[4 * i + 2] = wv[i].z; w[4 * i + 3] = wv[i].w;
    }

    const unsigned eb = (unsigned)e * 0x01010101u;
    int local = 0;
#pragma unroll
    for (int i = 0; i < 16; i++) local += __popc(__vcmpeq4(w[i], eb));
    local >>= 3;

    int incl = local;
#pragma unroll
    for (int off = 1; off < 32; off <<= 1) {
        int v = __shfl_up_sync(0xffffffffu, incl, off);
        if (lane >= off) incl += v;
    }
    if (lane == 31) warp_sums[wid] = incl;
    __syncthreads();
    int base = 0;
#pragma unroll
    for (int j = 0; j < 8; j++) base += (j < wid) ? warp_sums[j] : 0;

    int c = base + incl - local;   // exclusive prefix for this thread
#pragma unroll
    for (int i = 0; i < 16; i++) {
        unsigned word = w[i];
#pragma unroll
        for (int b = 0; b < 4; b++) {
            if (((word >> (8 * b)) & 0xffu) == (unsigned)e) {
                if (c < CAP) {
                    int fi = tid * 64 + i * 4 + b;
                    size_t off = (size_t)(fi >> 1) * (N_EXP * CAP)
                               + (size_t)e * CAP + c;
                    out_mask[off] = 1.0f;
                    out_comb[off] = g_top_w[fi];
                }
                c++;
            }
        }
    }
    if (tid == 255) {
        int total = base + incl;
        float f = (float)total / (float)FLAT;
        float p = g_psum[e] / (float)N_TOK;
        atomicAdd(out_loss, 0.01f * (float)N_EXP * f * p);
    }
}

// ---------------- launch ---------------------------------------------------
extern "C" void kernel_launch(void* const* d_in, const int* in_sizes, int n_in,
                              void* d_out, int out_size) {
    const float* x      = (const float*)d_in[0];
    const float* gate_w = (const float*)d_in[1];
    float* out = (float*)d_out;

    float* out_mask  = out;                                   // N*E*C
    float* out_comb  = out + (size_t)NEC;                     // N*E*C
    float* out_probs = out + (size_t)2 * NEC;                 // N*E
    float* out_loss  = out + (size_t)2 * NEC + (size_t)N_TOK * N_EXP;

    cudaFuncSetAttribute(k_mega,
        cudaFuncAttributeMaxDynamicSharedMemorySize, SMEM_BYTES);

    k_transpose_gate<<<(D_DIM * N_EXP) / 256, 256>>>(gate_w, out_loss);
    k_mega<<<GRID_TOTAL, 256, SMEM_BYTES>>>(x, out_probs, out);
    k_scan_scatter_loss<<<N_EXP, 256>>>(out_mask, out_comb, out_loss);
}

// round 13
// speedup vs baseline: 1.8405x; 1.0304x over previous
#include <cuda_runtime.h>
#include <cuda_bf16.h>
#include <math.h>
#include <stdint.h>

#define N_TOK   8192
#define D_DIM   4096
#define N_EXP   64
#define CAP     160                          // ceil(1.25*8192/64)
#define NEC     (N_TOK * N_EXP * CAP)        // 83,886,080
#define FLAT    (N_TOK * 2)                  // 16384

#define TILE_K  64
#define GEMM_GRID (N_TOK / 64)               // 128 blocks, 64 tokens each
#define LDS_S   68                           // smem row stride (floats)

// zero-fill: each GEMM block owns 2*NEC/128 floats = 327,680 float4,
// spread over 64 tiles = 5120 float4/tile = 20 per thread.
#define ZBLK4   327680
#define ZTILE4  5120

// dynamic smem layout (u32 units)
#define XB_OFF  0                            // x big   [64][68]
#define XS_OFF  4352                         // x small
#define GB_OFF  8704                         // gate big
#define GS_OFF  13056                        // gate small
#define SMEM_U32 17408
#define SMEM_BYTES (SMEM_U32 * 4)            // 69,632

// ---------------- device scratch ------------------------------------------
__device__ __align__(16) float g_gate_t[D_DIM * N_EXP];      // gate^T [k][e]
__device__ __align__(16) unsigned char g_top_idx8[FLAT];
__device__ __align__(16) float g_top_w[FLAT];
__device__ __align__(16) float g_psum[N_EXP];

__device__ __forceinline__ unsigned f2tf(float f) {
    unsigned r;
    asm("cvt.rna.tf32.f32 %0, %1;" : "=r"(r) : "f"(f));
    return r;
}
#define MMA_TF32(c0, c1, c2, c3, a0, a1, a2, a3, b0, b1)                      \
    asm volatile(                                                             \
        "mma.sync.aligned.m16n8k8.row.col.f32.tf32.tf32.f32 "                 \
        "{%0,%1,%2,%3}, {%4,%5,%6,%7}, {%8,%9}, {%0,%1,%2,%3};"               \
        : "+f"(c0), "+f"(c1), "+f"(c2), "+f"(c3)                              \
        : "r"(a0), "r"(a1), "r"(a2), "r"(a3), "r"(b0), "r"(b1))

// ---------------- gate transpose + all scratch init -----------------------
__global__ void k_transpose_gate(const float* __restrict__ gate_w,
                                 float* __restrict__ out_loss) {
    int idx = blockIdx.x * blockDim.x + threadIdx.x;   // covers D*E
    int k = idx >> 6;
    int e = idx & 63;
    g_gate_t[idx] = gate_w[(size_t)e * D_DIM + k];
    if (blockIdx.x == 0) {
        if (threadIdx.x < N_EXP) g_psum[threadIdx.x] = 0.0f;
        if (threadIdx.x == 64) out_loss[0] = 0.0f;
    }
}

// ---------------- 3xTF32 GEMM + interleaved zero-fill + softmax/top2 ------
__global__ void __launch_bounds__(256)
k_gemm(const float* __restrict__ x, float* __restrict__ probs_out,
       float4* __restrict__ zero_base /* mask+comb = 2*NEC floats */) {
    extern __shared__ unsigned sm[];
    __shared__ float smax[64], sinv[64];

    const int tid  = threadIdx.x;
    const int wid  = tid >> 5;
    const int lane = tid & 31;
    const int n0   = blockIdx.x * 64;

    const int wm = (wid & 3) * 16;       // token offset within block tile
    const int wn = (wid >> 2) * 32;      // expert offset

    float c[4][4];
#pragma unroll
    for (int nt = 0; nt < 4; nt++)
#pragma unroll
        for (int j = 0; j < 4; j++) c[nt][j] = 0.0f;

    const int g  = lane >> 2;            // 0..7
    const int t4 = lane & 3;             // 0..3
    const unsigned abase = (unsigned)((wm + g) * LDS_S + t4);
    const unsigned bbase = (unsigned)(t4 * LDS_S + wn + g);

    // this block's zero-fill region
    float4* zb = zero_base + (size_t)blockIdx.x * ZBLK4 + tid;
    const float4 z4 = make_float4(0.f, 0.f, 0.f, 0.f);

    // register prefetch of tile 0
    const int pr = tid >> 4;             // row 0..15 (stride 16 over l)
    const int pq = (tid & 15) * 4;       // col group
    float4 px[4], pg[4];
#pragma unroll
    for (int l = 0; l < 4; l++) {
        int r = pr + l * 16;
        px[l] = *(const float4*)&x[(size_t)(n0 + r) * D_DIM + pq];
        pg[l] = *(const float4*)&g_gate_t[(size_t)r * N_EXP + pq];
    }

    for (int kc = 0; kc < D_DIM; kc += TILE_K) {
        // ---- split + store prefetched tiles ------------------------------
#pragma unroll
        for (int l = 0; l < 4; l++) {
            int r = pr + l * 16;
            float4 v = px[l];
            unsigned b0 = f2tf(v.x), b1 = f2tf(v.y),
                     b2 = f2tf(v.z), b3 = f2tf(v.w);
            unsigned s0 = f2tf(v.x - __uint_as_float(b0));
            unsigned s1 = f2tf(v.y - __uint_as_float(b1));
            unsigned s2 = f2tf(v.z - __uint_as_float(b2));
            unsigned s3 = f2tf(v.w - __uint_as_float(b3));
            *(uint4*)&sm[XB_OFF + r * LDS_S + pq] = make_uint4(b0, b1, b2, b3);
            *(uint4*)&sm[XS_OFF + r * LDS_S + pq] = make_uint4(s0, s1, s2, s3);

            float4 w = pg[l];
            unsigned gb0 = f2tf(w.x), gb1 = f2tf(w.y),
                     gb2 = f2tf(w.z), gb3 = f2tf(w.w);
            unsigned gs0 = f2tf(w.x - __uint_as_float(gb0));
            unsigned gs1 = f2tf(w.y - __uint_as_float(gb1));
            unsigned gs2 = f2tf(w.z - __uint_as_float(gb2));
            unsigned gs3 = f2tf(w.w - __uint_as_float(gb3));
            *(uint4*)&sm[GB_OFF + r * LDS_S + pq] = make_uint4(gb0, gb1, gb2, gb3);
            *(uint4*)&sm[GS_OFF + r * LDS_S + pq] = make_uint4(gs0, gs1, gs2, gs3);
        }
        __syncthreads();

        // ---- prefetch next tile (drains under the MMA phase) -------------
        if (kc + TILE_K < D_DIM) {
#pragma unroll
            for (int l = 0; l < 4; l++) {
                int r = pr + l * 16;
                px[l] = *(const float4*)
                    &x[(size_t)(n0 + r) * D_DIM + kc + TILE_K + pq];
                pg[l] = *(const float4*)
                    &g_gate_t[(size_t)(kc + TILE_K + r) * N_EXP + pq];
            }
        }

        // ---- interleaved zero-fill: 20 streaming stores per thread -------
        // st.global.cs (evict-first): fire-and-forget, hides under MMAs,
        // doesn't pollute L2's resident gate matrix.
        {
            float4* z = zb + (kc >> 6) * ZTILE4;
#pragma unroll
            for (int j = 0; j < 20; j++) __stcs(&z[j * 256], z4);
        }

#pragma unroll
        for (int ks = 0; ks < 8; ks++) {
            const unsigned ao = abase + ks * 8;
            const unsigned bo = bbase + ks * 8 * LDS_S;
            unsigned ab0 = sm[XB_OFF + ao];
            unsigned ab1 = sm[XB_OFF + ao + 8 * LDS_S];
            unsigned ab2 = sm[XB_OFF + ao + 4];
            unsigned ab3 = sm[XB_OFF + ao + 8 * LDS_S + 4];
            unsigned as0 = sm[XS_OFF + ao];
            unsigned as1 = sm[XS_OFF + ao + 8 * LDS_S];
            unsigned as2 = sm[XS_OFF + ao + 4];
            unsigned as3 = sm[XS_OFF + ao + 8 * LDS_S + 4];
#pragma unroll
            for (int nt = 0; nt < 4; nt++) {
                unsigned bn = bo + nt * 8;
                unsigned bb0 = sm[GB_OFF + bn];
                unsigned bb1 = sm[GB_OFF + bn + 4 * LDS_S];
                unsigned bs0 = sm[GS_OFF + bn];
                unsigned bs1 = sm[GS_OFF + bn + 4 * LDS_S];
                MMA_TF32(c[nt][0], c[nt][1], c[nt][2], c[nt][3],
                         ab0, ab1, ab2, ab3, bb0, bb1);
                MMA_TF32(c[nt][0], c[nt][1], c[nt][2], c[nt][3],
                         ab0, ab1, ab2, ab3, bs0, bs1);
                MMA_TF32(c[nt][0], c[nt][1], c[nt][2], c[nt][3],
                         as0, as1, as2, as3, bb0, bb1);
            }
        }
        __syncthreads();
    }

    // ---- stage logits into smem (reuse XB region), [64][68] --------------
    float* lg = (float*)sm;
    {
        const int r0 = wm + g;
#pragma unroll
        for (int nt = 0; nt < 4; nt++) {
            int col = wn + nt * 8 + 2 * t4;
            lg[r0 * LDS_S + col]           = c[nt][0];
            lg[r0 * LDS_S + col + 1]       = c[nt][1];
            lg[(r0 + 8) * LDS_S + col]     = c[nt][2];
            lg[(r0 + 8) * LDS_S + col + 1] = c[nt][3];
        }
    }
    __syncthreads();

    // ---- per-token softmax stats + exact top-2 ---------------------------
    if (tid < 64) {
        const int t = tid;
        float m = -INFINITY;
#pragma unroll
        for (int e = 0; e < N_EXP; e++) m = fmaxf(m, lg[t * LDS_S + e]);
        float s = 0.0f;
#pragma unroll
        for (int e = 0; e < N_EXP; e++) s += expf(lg[t * LDS_S + e] - m);
        float inv = 1.0f / s;
        smax[t] = m;
        sinv[t] = inv;

        float v1 = -INFINITY, v2 = -INFINITY;
        int i1 = 0, i2 = 0;
#pragma unroll
        for (int e = 0; e < N_EXP; e++) {
            float v = lg[t * LDS_S + e];
            if (v > v1) { v2 = v1; i2 = i1; v1 = v; i1 = e; }
            else if (v > v2) { v2 = v; i2 = e; }
        }
        float p1 = expf(v1 - m) * inv;
        float p2 = expf(v2 - m) * inv;
        float r = 1.0f / (p1 + p2);
        int n = n0 + t;
        g_top_idx8[2 * n]     = (unsigned char)i1;
        g_top_idx8[2 * n + 1] = (unsigned char)i2;
        g_top_w[2 * n]     = p1 * r;
        g_top_w[2 * n + 1] = p2 * r;
    }
    __syncthreads();

    // ---- probs: 1 token x 16 experts per thread; keep p in lg ------------
    {
        int t = tid >> 2;
        int e0 = (tid & 3) * 16;
        float m = smax[t], inv = sinv[t];
        float buf[16];
#pragma unroll
        for (int i = 0; i < 16; i++)
            buf[i] = expf(lg[t * LDS_S + e0 + i] - m) * inv;
        float4* dst = (float4*)&probs_out[(size_t)(n0 + t) * N_EXP + e0];
#pragma unroll
        for (int q = 0; q < 4; q++)
            dst[q] = make_float4(buf[4 * q], buf[4 * q + 1],
                                 buf[4 * q + 2], buf[4 * q + 3]);
#pragma unroll
        for (int i = 0; i < 16; i++) lg[t * LDS_S + e0 + i] = buf[i];
    }
    __syncthreads();

    if (tid < 64) {
        const int e = tid;
        float s = 0.0f;
#pragma unroll
        for (int t = 0; t < 64; t++) s += lg[t * LDS_S + e];
        atomicAdd(&g_psum[e], s);
    }
}

// ---------------- scan + scatter + loss (one block per expert) ------------
__global__ void __launch_bounds__(256)
k_scan_scatter_loss(float* __restrict__ out_mask,
                    float* __restrict__ out_comb,
                    float* __restrict__ out_loss) {
    __shared__ int warp_sums[8];
    const int e = blockIdx.x;
    const int tid = threadIdx.x;
    const int lane = tid & 31;
    const int wid = tid >> 5;

    uint4 wv[4];
#pragma unroll
    for (int i = 0; i < 4; i++)
        wv[i] = ((const uint4*)g_top_idx8)[tid * 4 + i];
    unsigned w[16];
#pragma unroll
    for (int i = 0; i < 4; i++) {
        w[4 * i + 0] = wv[i].x; w[4 * i + 1] = wv[i].y;
        w[4 * i + 2] = wv[i].z; w[4 * i + 3] = wv[i].w;
    }

    const unsigned eb = (unsigned)e * 0x01010101u;
    int local = 0;
#pragma unroll
    for (int i = 0; i < 16; i++) local += __popc(__vcmpeq4(w[i], eb));
    local >>= 3;

    int incl = local;
#pragma unroll
    for (int off = 1; off < 32; off <<= 1) {
        int v = __shfl_up_sync(0xffffffffu, incl, off);
        if (lane >= off) incl += v;
    }
    if (lane == 31) warp_sums[wid] = incl;
    __syncthreads();
    int base = 0;
#pragma unroll
    for (int j = 0; j < 8; j++) base += (j < wid) ? warp_sums[j] : 0;

    int c = base + incl - local;   // exclusive prefix for this thread
#pragma unroll
    for (int i = 0; i < 16; i++) {
        unsigned word = w[i];
#pragma unroll
        for (int b = 0; b < 4; b++) {
            if (((word >> (8 * b)) & 0xffu) == (unsigned)e) {
                if (c < CAP) {
                    int fi = tid * 64 + i * 4 + b;
                    size_t off = (size_t)(fi >> 1) * (N_EXP * CAP)
                               + (size_t)e * CAP + c;
                    out_mask[off] = 1.0f;
                    out_comb[off] = g_top_w[fi];
                }
                c++;
            }
        }
    }
    if (tid == 255) {
        int total = base + incl;
        float f = (float)total / (float)FLAT;
        float p = g_psum[e] / (float)N_TOK;
        atomicAdd(out_loss, 0.01f * (float)N_EXP * f * p);
    }
}

// ---------------- launch (single stream, no events) ------------------------
extern "C" void kernel_launch(void* const* d_in, const int* in_sizes, int n_in,
                              void* d_out, int out_size) {
    const float* x      = (const float*)d_in[0];
    const float* gate_w = (const float*)d_in[1];
    float* out = (float*)d_out;

    float* out_mask  = out;                                   // N*E*C
    float* out_comb  = out + (size_t)NEC;                     // N*E*C
    float* out_probs = out + (size_t)2 * NEC;                 // N*E
    float* out_loss  = out + (size_t)2 * NEC + (size_t)N_TOK * N_EXP;

    cudaFuncSetAttribute(k_gemm,
        cudaFuncAttributeMaxDynamicSharedMemorySize, SMEM_BYTES);

    k_transpose_gate<<<(D_DIM * N_EXP) / 256, 256>>>(gate_w, out_loss);
    k_gemm<<<GEMM_GRID, 256, SMEM_BYTES>>>(x, out_probs, (float4*)out);
    k_scan_scatter_loss<<<N_EXP, 256>>>(out_mask, out_comb, out_loss);
}

// round 14
// speedup vs baseline: 2.0339x; 1.1051x over previous
#include <cuda_runtime.h>
#include <cuda_bf16.h>
#include <math.h>
#include <stdint.h>

#define N_TOK   8192
#define D_DIM   4096
#define N_EXP   64
#define CAP     160                          // ceil(1.25*8192/64)
#define NEC     (N_TOK * N_EXP * CAP)        // 83,886,080
#define FLAT    (N_TOK * 2)                  // 16384

#define TILE_K  64
#define GEMM_GRID (N_TOK / 64)               // 128 blocks, 64 tokens each
#define LDS_S   68                           // smem row stride (floats)

// zero-fill: each GEMM block owns 2*NEC/128 floats = 327,680 float4,
// spread over 64 tiles = 5120 float4/tile = 20 per thread.
#define ZBLK4   327680
#define ZTILE4  5120

// dynamic smem layout (u32 units)
#define XB_OFF  0                            // x big   [64][68]
#define XS_OFF  4352                         // x small
#define GB_OFF  8704                         // gate big
#define GS_OFF  13056                        // gate small
#define SMEM_U32 17408
#define SMEM_BYTES (SMEM_U32 * 4)            // 69,632

// ---------------- device scratch ------------------------------------------
__device__ __align__(16) unsigned g_gate_big[D_DIM * N_EXP];   // tf32 [k][e]
__device__ __align__(16) unsigned g_gate_small[D_DIM * N_EXP]; // tf32 [k][e]
__device__ __align__(16) unsigned char g_top_idx8[FLAT];
__device__ __align__(16) float g_top_w[FLAT];
__device__ __align__(16) float g_psum[N_EXP];

__device__ __forceinline__ unsigned f2tf(float f) {
    unsigned r;
    asm("cvt.rna.tf32.f32 %0, %1;" : "=r"(r) : "f"(f));
    return r;
}
#define MMA_TF32(c0, c1, c2, c3, a0, a1, a2, a3, b0, b1)                      \
    asm volatile(                                                             \
        "mma.sync.aligned.m16n8k8.row.col.f32.tf32.tf32.f32 "                 \
        "{%0,%1,%2,%3}, {%4,%5,%6,%7}, {%8,%9}, {%0,%1,%2,%3};"               \
        : "+f"(c0), "+f"(c1), "+f"(c2), "+f"(c3)                              \
        : "r"(a0), "r"(a1), "r"(a2), "r"(a3), "r"(b0), "r"(b1))

// ---------------- prep: transpose + 3xTF32-split gate + scratch init ------
__global__ void k_prep(const float* __restrict__ gate_w,
                       float* __restrict__ out_loss) {
    int idx = blockIdx.x * blockDim.x + threadIdx.x;   // covers D*E
    int k = idx >> 6;
    int e = idx & 63;
    float v = gate_w[(size_t)e * D_DIM + k];
    unsigned b = f2tf(v);
    g_gate_big[idx]   = b;
    g_gate_small[idx] = f2tf(v - __uint_as_float(b));
    if (blockIdx.x == 0) {
        if (threadIdx.x < N_EXP) g_psum[threadIdx.x] = 0.0f;
        if (threadIdx.x == 64) out_loss[0] = 0.0f;
    }
}

// ---------------- 3xTF32 GEMM + interleaved zero-fill + softmax/top2 ------
__global__ void __launch_bounds__(256)
k_gemm(const float* __restrict__ x, float* __restrict__ probs_out,
       float4* __restrict__ zero_base /* mask+comb = 2*NEC floats */) {
    extern __shared__ unsigned sm[];
    __shared__ float smax[64], sinv[64];

    const int tid  = threadIdx.x;
    const int wid  = tid >> 5;
    const int lane = tid & 31;
    const int n0   = blockIdx.x * 64;

    const int wm = (wid & 3) * 16;       // token offset within block tile
    const int wn = (wid >> 2) * 32;      // expert offset

    float c[4][4];
#pragma unroll
    for (int nt = 0; nt < 4; nt++)
#pragma unroll
        for (int j = 0; j < 4; j++) c[nt][j] = 0.0f;

    const int g  = lane >> 2;            // 0..7
    const int t4 = lane & 3;             // 0..3
    const unsigned abase = (unsigned)((wm + g) * LDS_S + t4);
    const unsigned bbase = (unsigned)(t4 * LDS_S + wn + g);

    // this block's zero-fill region
    float4* zb = zero_base + (size_t)blockIdx.x * ZBLK4 + tid;
    const float4 z4 = make_float4(0.f, 0.f, 0.f, 0.f);

    // register prefetch of tile 0
    const int pr = tid >> 4;             // row 0..15 (stride 16 over l)
    const int pq = (tid & 15) * 4;       // col group
    float4 px[4];
    uint4  pgb[4], pgs[4];
#pragma unroll
    for (int l = 0; l < 4; l++) {
        int r = pr + l * 16;
        px[l]  = *(const float4*)&x[(size_t)(n0 + r) * D_DIM + pq];
        pgb[l] = *(const uint4*)&g_gate_big[(size_t)r * N_EXP + pq];
        pgs[l] = *(const uint4*)&g_gate_small[(size_t)r * N_EXP + pq];
    }

    for (int kc = 0; kc < D_DIM; kc += TILE_K) {
        // ---- split x + store all prefetched tiles ------------------------
#pragma unroll
        for (int l = 0; l < 4; l++) {
            int r = pr + l * 16;
            float4 v = px[l];
            unsigned b0 = f2tf(v.x), b1 = f2tf(v.y),
                     b2 = f2tf(v.z), b3 = f2tf(v.w);
            unsigned s0 = f2tf(v.x - __uint_as_float(b0));
            unsigned s1 = f2tf(v.y - __uint_as_float(b1));
            unsigned s2 = f2tf(v.z - __uint_as_float(b2));
            unsigned s3 = f2tf(v.w - __uint_as_float(b3));
            *(uint4*)&sm[XB_OFF + r * LDS_S + pq] = make_uint4(b0, b1, b2, b3);
            *(uint4*)&sm[XS_OFF + r * LDS_S + pq] = make_uint4(s0, s1, s2, s3);
            *(uint4*)&sm[GB_OFF + r * LDS_S + pq] = pgb[l];
            *(uint4*)&sm[GS_OFF + r * LDS_S + pq] = pgs[l];
        }
        __syncthreads();

        // ---- prefetch next tile (drains under the MMA phase) -------------
        if (kc + TILE_K < D_DIM) {
#pragma unroll
            for (int l = 0; l < 4; l++) {
                int r = pr + l * 16;
                px[l] = *(const float4*)
                    &x[(size_t)(n0 + r) * D_DIM + kc + TILE_K + pq];
                pgb[l] = *(const uint4*)
                    &g_gate_big[(size_t)(kc + TILE_K + r) * N_EXP + pq];
                pgs[l] = *(const uint4*)
                    &g_gate_small[(size_t)(kc + TILE_K + r) * N_EXP + pq];
            }
        }

        // ---- interleaved zero-fill: 20 streaming stores per thread -------
        {
            float4* z = zb + (kc >> 6) * ZTILE4;
#pragma unroll
            for (int j = 0; j < 20; j++) __stcs(&z[j * 256], z4);
        }

#pragma unroll
        for (int ks = 0; ks < 8; ks++) {
            const unsigned ao = abase + ks * 8;
            const unsigned bo = bbase + ks * 8 * LDS_S;
            unsigned ab0 = sm[XB_OFF + ao];
            unsigned ab1 = sm[XB_OFF + ao + 8 * LDS_S];
            unsigned ab2 = sm[XB_OFF + ao + 4];
            unsigned ab3 = sm[XB_OFF + ao + 8 * LDS_S + 4];
            unsigned as0 = sm[XS_OFF + ao];
            unsigned as1 = sm[XS_OFF + ao + 8 * LDS_S];
            unsigned as2 = sm[XS_OFF + ao + 4];
            unsigned as3 = sm[XS_OFF + ao + 8 * LDS_S + 4];
#pragma unroll
            for (int nt = 0; nt < 4; nt++) {
                unsigned bn = bo + nt * 8;
                unsigned bb0 = sm[GB_OFF + bn];
                unsigned bb1 = sm[GB_OFF + bn + 4 * LDS_S];
                unsigned bs0 = sm[GS_OFF + bn];
                unsigned bs1 = sm[GS_OFF + bn + 4 * LDS_S];
                MMA_TF32(c[nt][0], c[nt][1], c[nt][2], c[nt][3],
                         ab0, ab1, ab2, ab3, bb0, bb1);
                MMA_TF32(c[nt][0], c[nt][1], c[nt][2], c[nt][3],
                         ab0, ab1, ab2, ab3, bs0, bs1);
                MMA_TF32(c[nt][0], c[nt][1], c[nt][2], c[nt][3],
                         as0, as1, as2, as3, bb0, bb1);
            }
        }
        __syncthreads();
    }

    // ---- stage logits into smem (reuse XB region), [64][68] --------------
    float* lg = (float*)sm;
    {
        const int r0 = wm + g;
#pragma unroll
        for (int nt = 0; nt < 4; nt++) {
            int col = wn + nt * 8 + 2 * t4;
            lg[r0 * LDS_S + col]           = c[nt][0];
            lg[r0 * LDS_S + col + 1]       = c[nt][1];
            lg[(r0 + 8) * LDS_S + col]     = c[nt][2];
            lg[(r0 + 8) * LDS_S + col + 1] = c[nt][3];
        }
    }
    __syncthreads();

    // ---- per-token softmax stats + exact top-2 ---------------------------
    if (tid < 64) {
        const int t = tid;
        float m = -INFINITY;
#pragma unroll
        for (int e = 0; e < N_EXP; e++) m = fmaxf(m, lg[t * LDS_S + e]);
        float s = 0.0f;
#pragma unroll
        for (int e = 0; e < N_EXP; e++) s += expf(lg[t * LDS_S + e] - m);
        float inv = 1.0f / s;
        smax[t] = m;
        sinv[t] = inv;

        float v1 = -INFINITY, v2 = -INFINITY;
        int i1 = 0, i2 = 0;
#pragma unroll
        for (int e = 0; e < N_EXP; e++) {
            float v = lg[t * LDS_S + e];
            if (v > v1) { v2 = v1; i2 = i1; v1 = v; i1 = e; }
            else if (v > v2) { v2 = v; i2 = e; }
        }
        float p1 = expf(v1 - m) * inv;
        float p2 = expf(v2 - m) * inv;
        float r = 1.0f / (p1 + p2);
        int n = n0 + t;
        g_top_idx8[2 * n]     = (unsigned char)i1;
        g_top_idx8[2 * n + 1] = (unsigned char)i2;
        g_top_w[2 * n]     = p1 * r;
        g_top_w[2 * n + 1] = p2 * r;
    }
    __syncthreads();

    // ---- probs: 1 token x 16 experts per thread; keep p in lg ------------
    {
        int t = tid >> 2;
        int e0 = (tid & 3) * 16;
        float m = smax[t], inv = sinv[t];
        float buf[16];
#pragma unroll
        for (int i = 0; i < 16; i++)
            buf[i] = expf(lg[t * LDS_S + e0 + i] - m) * inv;
        float4* dst = (float4*)&probs_out[(size_t)(n0 + t) * N_EXP + e0];
#pragma unroll
        for (int q = 0; q < 4; q++)
            dst[q] = make_float4(buf[4 * q], buf[4 * q + 1],
                                 buf[4 * q + 2], buf[4 * q + 3]);
#pragma unroll
        for (int i = 0; i < 16; i++) lg[t * LDS_S + e0 + i] = buf[i];
    }
    __syncthreads();

    if (tid < 64) {
        const int e = tid;
        float s = 0.0f;
#pragma unroll
        for (int t = 0; t < 64; t++) s += lg[t * LDS_S + e];
        atomicAdd(&g_psum[e], s);
    }
}

// ---------------- scan + scatter + loss (one block per expert) ------------
__global__ void __launch_bounds__(256)
k_scan_scatter_loss(float* __restrict__ out_mask,
                    float* __restrict__ out_comb,
                    float* __restrict__ out_loss) {
    __shared__ int warp_sums[8];
    const int e = blockIdx.x;
    const int tid = threadIdx.x;
    const int lane = tid & 31;
    const int wid = tid >> 5;

    uint4 wv[4];
#pragma unroll
    for (int i = 0; i < 4; i++)
        wv[i] = ((const uint4*)g_top_idx8)[tid * 4 + i];
    unsigned w[16];
#pragma unroll
    for (int i = 0; i < 4; i++) {
        w[4 * i + 0] = wv[i].x; w[4 * i + 1] = wv[i].y;
        w[4 * i + 2] = wv[i].z; w[4 * i + 3] = wv[i].w;
    }

    const unsigned eb = (unsigned)e * 0x01010101u;
    int local = 0;
#pragma unroll
    for (int i = 0; i < 16; i++) local += __popc(__vcmpeq4(w[i], eb));
    local >>= 3;

    int incl = local;
#pragma unroll
    for (int off = 1; off < 32; off <<= 1) {
        int v = __shfl_up_sync(0xffffffffu, incl, off);
        if (lane >= off) incl += v;
    }
    if (lane == 31) warp_sums[wid] = incl;
    __syncthreads();
    int base = 0;
#pragma unroll
    for (int j = 0; j < 8; j++) base += (j < wid) ? warp_sums[j] : 0;

    int c = base + incl - local;   // exclusive prefix for this thread
#pragma unroll
    for (int i = 0; i < 16; i++) {
        unsigned word = w[i];
#pragma unroll
        for (int b = 0; b < 4; b++) {
            if (((word >> (8 * b)) & 0xffu) == (unsigned)e) {
                if (c < CAP) {
                    int fi = tid * 64 + i * 4 + b;
                    size_t off = (size_t)(fi >> 1) * (N_EXP * CAP)
                               + (size_t)e * CAP + c;
                    out_mask[off] = 1.0f;
                    out_comb[off] = g_top_w[fi];
                }
                c++;
            }
        }
    }
    if (tid == 255) {
        int total = base + incl;
        float f = (float)total / (float)FLAT;
        float p = g_psum[e] / (float)N_TOK;
        atomicAdd(out_loss, 0.01f * (float)N_EXP * f * p);
    }
}

// ---------------- launch (single stream) -----------------------------------
extern "C" void kernel_launch(void* const* d_in, const int* in_sizes, int n_in,
                              void* d_out, int out_size) {
    const float* x      = (const float*)d_in[0];
    const float* gate_w = (const float*)d_in[1];
    float* out = (float*)d_out;

    float* out_mask  = out;                                   // N*E*C
    float* out_comb  = out + (size_t)NEC;                     // N*E*C
    float* out_probs = out + (size_t)2 * NEC;                 // N*E
    float* out_loss  = out + (size_t)2 * NEC + (size_t)N_TOK * N_EXP;

    cudaFuncSetAttribute(k_gemm,
        cudaFuncAttributeMaxDynamicSharedMemorySize, SMEM_BYTES);

    k_prep<<<(D_DIM * N_EXP) / 256, 256>>>(gate_w, out_loss);
    k_gemm<<<GEMM_GRID, 256, SMEM_BYTES>>>(x, out_probs, (float4*)out);
    k_scan_scatter_loss<<<N_EXP, 256>>>(out_mask, out_comb, out_loss);
}

// round 15
// speedup vs baseline: 2.1163x; 1.0405x over previous
#include <cuda_runtime.h>
#include <cuda_bf16.h>
#include <math.h>
#include <stdint.h>

#define N_TOK   8192
#define D_DIM   4096
#define N_EXP   64
#define CAP     160                          // ceil(1.25*8192/64)
#define NEC     (N_TOK * N_EXP * CAP)        // 83,886,080
#define FLAT    (N_TOK * 2)                  // 16384

#define TILE_K  64
#define NT      (D_DIM / TILE_K)             // 64 tiles
#define GEMM_GRID (N_TOK / 64)               // 128 blocks, 64 tokens each
#define LDS_S   68                           // smem row stride (u32)

// zero-fill: each GEMM block owns 2*NEC/128 floats = 327,680 float4,
// spread over 64 tiles = 5120 float4/tile = 20 per thread.
#define ZBLK4   327680
#define ZTILE4  5120

// dynamic smem: TWO buffers of 4 regions [64][68] u32
#define XB_OFF  0
#define XS_OFF  4352
#define GB_OFF  8704
#define GS_OFF  13056
#define BUF_U32 17408                        // one buffer
#define SMEM_U32 (2 * BUF_U32)
#define SMEM_BYTES (SMEM_U32 * 4)            // 139,264

// ---------------- device scratch ------------------------------------------
__device__ __align__(16) unsigned g_gate_big[D_DIM * N_EXP];   // tf32 [k][e]
__device__ __align__(16) unsigned g_gate_small[D_DIM * N_EXP]; // tf32 [k][e]
__device__ __align__(16) unsigned char g_top_idx8[FLAT];
__device__ __align__(16) float g_top_w[FLAT];
__device__ __align__(16) float g_psum[N_EXP];

__device__ __forceinline__ unsigned f2tf(float f) {
    unsigned r;
    asm("cvt.rna.tf32.f32 %0, %1;" : "=r"(r) : "f"(f));
    return r;
}
#define MMA_TF32(c0, c1, c2, c3, a0, a1, a2, a3, b0, b1)                      \
    asm volatile(                                                             \
        "mma.sync.aligned.m16n8k8.row.col.f32.tf32.tf32.f32 "                 \
        "{%0,%1,%2,%3}, {%4,%5,%6,%7}, {%8,%9}, {%0,%1,%2,%3};"               \
        : "+f"(c0), "+f"(c1), "+f"(c2), "+f"(c3)                              \
        : "r"(a0), "r"(a1), "r"(a2), "r"(a3), "r"(b0), "r"(b1))

// ---------------- prep: transpose + 3xTF32-split gate + scratch init ------
__global__ void k_prep(const float* __restrict__ gate_w,
                       float* __restrict__ out_loss) {
    int idx = blockIdx.x * blockDim.x + threadIdx.x;   // covers D*E
    int k = idx >> 6;
    int e = idx & 63;
    float v = gate_w[(size_t)e * D_DIM + k];
    unsigned b = f2tf(v);
    g_gate_big[idx]   = b;
    g_gate_small[idx] = f2tf(v - __uint_as_float(b));
    if (blockIdx.x == 0) {
        if (threadIdx.x < N_EXP) g_psum[threadIdx.x] = 0.0f;
        if (threadIdx.x == 64) out_loss[0] = 0.0f;
    }
}

// ---------------- 3xTF32 GEMM, double-buffered + zero-fill + topk ---------
__global__ void __launch_bounds__(256)
k_gemm(const float* __restrict__ x, float* __restrict__ probs_out,
       float4* __restrict__ zero_base /* mask+comb = 2*NEC floats */) {
    extern __shared__ unsigned sm[];
    __shared__ float smax[64], sinv[64];

    const int tid  = threadIdx.x;
    const int wid  = tid >> 5;
    const int lane = tid & 31;
    const int n0   = blockIdx.x * 64;

    const int wm = (wid & 3) * 16;       // token offset within block tile
    const int wn = (wid >> 2) * 32;      // expert offset

    float c[4][4];
#pragma unroll
    for (int nt = 0; nt < 4; nt++)
#pragma unroll
        for (int j = 0; j < 4; j++) c[nt][j] = 0.0f;

    const int g  = lane >> 2;            // 0..7
    const int t4 = lane & 3;             // 0..3
    const unsigned abase = (unsigned)((wm + g) * LDS_S + t4);
    const unsigned bbase = (unsigned)(t4 * LDS_S + wn + g);

    float4* zb = zero_base + (size_t)blockIdx.x * ZBLK4 + tid;
    const float4 z4 = make_float4(0.f, 0.f, 0.f, 0.f);

    const int pr = tid >> 4;             // row 0..15 (stride 16 over l)
    const int pq = (tid & 15) * 4;       // col group
    float4 px[4];
    uint4  pgb[4], pgs[4];

    // helper lambdas (inlined by compiler)
    auto ldg_tile = [&](int t) {
        const size_t kb = (size_t)t * TILE_K;
#pragma unroll
        for (int l = 0; l < 4; l++) {
            int r = pr + l * 16;
            px[l]  = *(const float4*)&x[(size_t)(n0 + r) * D_DIM + kb + pq];
            pgb[l] = *(const uint4*)&g_gate_big[(kb + r) * N_EXP + pq];
            pgs[l] = *(const uint4*)&g_gate_small[(kb + r) * N_EXP + pq];
        }
    };
    auto split_store = [&](int buf) {
        unsigned* b = sm + buf * BUF_U32;
#pragma unroll
        for (int l = 0; l < 4; l++) {
            int r = pr + l * 16;
            float4 v = px[l];
            unsigned b0 = f2tf(v.x), b1 = f2tf(v.y),
                     b2 = f2tf(v.z), b3 = f2tf(v.w);
            unsigned s0 = f2tf(v.x - __uint_as_float(b0));
            unsigned s1 = f2tf(v.y - __uint_as_float(b1));
            unsigned s2 = f2tf(v.z - __uint_as_float(b2));
            unsigned s3 = f2tf(v.w - __uint_as_float(b3));
            *(uint4*)&b[XB_OFF + r * LDS_S + pq] = make_uint4(b0, b1, b2, b3);
            *(uint4*)&b[XS_OFF + r * LDS_S + pq] = make_uint4(s0, s1, s2, s3);
            *(uint4*)&b[GB_OFF + r * LDS_S + pq] = pgb[l];
            *(uint4*)&b[GS_OFF + r * LDS_S + pq] = pgs[l];
        }
    };

    // ---- prologue: tile0 -> buf0; tile1 -> regs --------------------------
    ldg_tile(0);
    split_store(0);
    ldg_tile(1);
    __syncthreads();

    for (int t = 0; t < NT; t++) {
        const int cur = t & 1;
        const unsigned* b = sm + cur * BUF_U32;

        // 1. split+store tile t+1 (regs) into the other buffer
        if (t < NT - 1) split_store(1 - cur);

        // 2. interleaved zero-fill (streaming, evict-first)
        {
            float4* z = zb + t * ZTILE4;
#pragma unroll
            for (int j = 0; j < 20; j++) __stcs(&z[j * 256], z4);
        }

        // 3. LDG prefetch tile t+2
        if (t < NT - 2) ldg_tile(t + 2);

        // 4. MMA from current buffer
#pragma unroll
        for (int ks = 0; ks < 8; ks++) {
            const unsigned ao = abase + ks * 8;
            const unsigned bo = bbase + ks * 8 * LDS_S;
            unsigned ab0 = b[XB_OFF + ao];
            unsigned ab1 = b[XB_OFF + ao + 8 * LDS_S];
            unsigned ab2 = b[XB_OFF + ao + 4];
            unsigned ab3 = b[XB_OFF + ao + 8 * LDS_S + 4];
            unsigned as0 = b[XS_OFF + ao];
            unsigned as1 = b[XS_OFF + ao + 8 * LDS_S];
            unsigned as2 = b[XS_OFF + ao + 4];
            unsigned as3 = b[XS_OFF + ao + 8 * LDS_S + 4];
#pragma unroll
            for (int nt = 0; nt < 4; nt++) {
                unsigned bn = bo + nt * 8;
                unsigned bb0 = b[GB_OFF + bn];
                unsigned bb1 = b[GB_OFF + bn + 4 * LDS_S];
                unsigned bs0 = b[GS_OFF + bn];
                unsigned bs1 = b[GS_OFF + bn + 4 * LDS_S];
                MMA_TF32(c[nt][0], c[nt][1], c[nt][2], c[nt][3],
                         ab0, ab1, ab2, ab3, bb0, bb1);
                MMA_TF32(c[nt][0], c[nt][1], c[nt][2], c[nt][3],
                         ab0, ab1, ab2, ab3, bs0, bs1);
                MMA_TF32(c[nt][0], c[nt][1], c[nt][2], c[nt][3],
                         as0, as1, as2, as3, bb0, bb1);
            }
        }
        __syncthreads();   // one barrier per tile
    }

    // ---- stage logits into smem (reuse buffer0 XB region), [64][68] ------
    float* lg = (float*)sm;
    {
        const int r0 = wm + g;
#pragma unroll
        for (int nt = 0; nt < 4; nt++) {
            int col = wn + nt * 8 + 2 * t4;
            lg[r0 * LDS_S + col]           = c[nt][0];
            lg[r0 * LDS_S + col + 1]       = c[nt][1];
            lg[(r0 + 8) * LDS_S + col]     = c[nt][2];
            lg[(r0 + 8) * LDS_S + col + 1] = c[nt][3];
        }
    }
    __syncthreads();

    // ---- per-token softmax stats + exact top-2 ---------------------------
    if (tid < 64) {
        const int t = tid;
        float m = -INFINITY;
#pragma unroll
        for (int e = 0; e < N_EXP; e++) m = fmaxf(m, lg[t * LDS_S + e]);
        float s = 0.0f;
#pragma unroll
        for (int e = 0; e < N_EXP; e++) s += expf(lg[t * LDS_S + e] - m);
        float inv = 1.0f / s;
        smax[t] = m;
        sinv[t] = inv;

        float v1 = -INFINITY, v2 = -INFINITY;
        int i1 = 0, i2 = 0;
#pragma unroll
        for (int e = 0; e < N_EXP; e++) {
            float v = lg[t * LDS_S + e];
            if (v > v1) { v2 = v1; i2 = i1; v1 = v; i1 = e; }
            else if (v > v2) { v2 = v; i2 = e; }
        }
        float p1 = expf(v1 - m) * inv;
        float p2 = expf(v2 - m) * inv;
        float r = 1.0f / (p1 + p2);
        int n = n0 + t;
        g_top_idx8[2 * n]     = (unsigned char)i1;
        g_top_idx8[2 * n + 1] = (unsigned char)i2;
        g_top_w[2 * n]     = p1 * r;
        g_top_w[2 * n + 1] = p2 * r;
    }
    __syncthreads();

    // ---- probs: 1 token x 16 experts per thread; keep p in lg ------------
    {
        int t = tid >> 2;
        int e0 = (tid & 3) * 16;
        float m = smax[t], inv = sinv[t];
        float buf[16];
#pragma unroll
        for (int i = 0; i < 16; i++)
            buf[i] = expf(lg[t * LDS_S + e0 + i] - m) * inv;
        float4* dst = (float4*)&probs_out[(size_t)(n0 + t) * N_EXP + e0];
#pragma unroll
        for (int q = 0; q < 4; q++)
            dst[q] = make_float4(buf[4 * q], buf[4 * q + 1],
                                 buf[4 * q + 2], buf[4 * q + 3]);
#pragma unroll
        for (int i = 0; i < 16; i++) lg[t * LDS_S + e0 + i] = buf[i];
    }
    __syncthreads();

    if (tid < 64) {
        const int e = tid;
        float s = 0.0f;
#pragma unroll
        for (int t = 0; t < 64; t++) s += lg[t * LDS_S + e];
        atomicAdd(&g_psum[e], s);
    }
}

// ---------------- scan + scatter + loss (one block per expert) ------------
__global__ void __launch_bounds__(256)
k_scan_scatter_loss(float* __restrict__ out_mask,
                    float* __restrict__ out_comb,
                    float* __restrict__ out_loss) {
    __shared__ int warp_sums[8];
    const int e = blockIdx.x;
    const int tid = threadIdx.x;
    const int lane = tid & 31;
    const int wid = tid >> 5;

    uint4 wv[4];
#pragma unroll
    for (int i = 0; i < 4; i++)
        wv[i] = ((const uint4*)g_top_idx8)[tid * 4 + i];
    unsigned w[16];
#pragma unroll
    for (int i = 0; i < 4; i++) {
        w[4 * i + 0] = wv[i].x; w[4 * i + 1] = wv[i].y;
        w[4 * i + 2] = wv[i].z; w[4 * i + 3] = wv[i].w;
    }

    const unsigned eb = (unsigned)e * 0x01010101u;
    int local = 0;
#pragma unroll
    for (int i = 0; i < 16; i++) local += __popc(__vcmpeq4(w[i], eb));
    local >>= 3;

    int incl = local;
#pragma unroll
    for (int off = 1; off < 32; off <<= 1) {
        int v = __shfl_up_sync(0xffffffffu, incl, off);
        if (lane >= off) incl += v;
    }
    if (lane == 31) warp_sums[wid] = incl;
    __syncthreads();
    int base = 0;
#pragma unroll
    for (int j = 0; j < 8; j++) base += (j < wid) ? warp_sums[j] : 0;

    int c = base + incl - local;   // exclusive prefix for this thread
#pragma unroll
    for (int i = 0; i < 16; i++) {
        unsigned word = w[i];
#pragma unroll
        for (int b = 0; b < 4; b++) {
            if (((word >> (8 * b)) & 0xffu) == (unsigned)e) {
                if (c < CAP) {
                    int fi = tid * 64 + i * 4 + b;
                    size_t off = (size_t)(fi >> 1) * (N_EXP * CAP)
                               + (size_t)e * CAP + c;
                    out_mask[off] = 1.0f;
                    out_comb[off] = g_top_w[fi];
                }
                c++;
            }
        }
    }
    if (tid == 255) {
        int total = base + incl;
        float f = (float)total / (float)FLAT;
        float p = g_psum[e] / (float)N_TOK;
        atomicAdd(out_loss, 0.01f * (float)N_EXP * f * p);
    }
}

// ---------------- launch (single stream) -----------------------------------
extern "C" void kernel_launch(void* const* d_in, const int* in_sizes, int n_in,
                              void* d_out, int out_size) {
    const float* x      = (const float*)d_in[0];
    const float* gate_w = (const float*)d_in[1];
    float* out = (float*)d_out;

    float* out_mask  = out;                                   // N*E*C
    float* out_comb  = out + (size_t)NEC;                     // N*E*C
    float* out_probs = out + (size_t)2 * NEC;                 // N*E
    float* out_loss  = out + (size_t)2 * NEC + (size_t)N_TOK * N_EXP;

    cudaFuncSetAttribute(k_gemm,
        cudaFuncAttributeMaxDynamicSharedMemorySize, SMEM_BYTES);

    k_prep<<<(D_DIM * N_EXP) / 256, 256>>>(gate_w, out_loss);
    k_gemm<<<GEMM_GRID, 256, SMEM_BYTES>>>(x, out_probs, (float4*)out);
    k_scan_scatter_loss<<<N_EXP, 256>>>(out_mask, out_comb, out_loss);
}